// round 1
// baseline (speedup 1.0000x reference)
#include <cuda_runtime.h>

// Problem dims (fixed by the reference): video (B,C,T,H,W) fp32
#define BB 4
#define CC 3
#define TF 103
#define HH 224
#define WW 224
#define W4 (WW / 4)                       // 56 float4 per row
#define N4 (BB * CC * TF * HH * W4)       // 15,504,384 float4 outputs

// Per-(b,t) rectangles, precomputed once per launch.
// self rect = clamped "mask"; idx rect = unclamped m_br of bbox[index[b]].
__device__ int4 g_self_rect[BB * TF];  // x0, x1, y0, y1 (inclusive)
__device__ int4 g_idx_rect[BB * TF];
__device__ int  g_index[BB];

__global__ void rect_kernel(const float* __restrict__ bbox,
                            const int* __restrict__ index) {
    int i = blockIdx.x * blockDim.x + threadIdx.x;
    if (i >= BB * TF) return;
    int b = i / TF;
    int t = i % TF;

    // --- self (clamped) mask rect ---
    const float* p = bbox + (size_t)(b * TF + t) * 8;
    float xmn = fminf(fminf(p[0], p[2]), fminf(p[4], p[6]));
    float xmx = fmaxf(fmaxf(p[0], p[2]), fmaxf(p[4], p[6]));
    float ymn = fminf(fminf(p[1], p[3]), fminf(p[5], p[7]));
    float ymx = fmaxf(fmaxf(p[1], p[3]), fmaxf(p[5], p[7]));
    int4 rs;
    rs.x = (int)fmaxf(xmn, 0.0f);
    rs.y = (int)fminf(xmx, (float)WW);
    rs.z = (int)fmaxf(ymn, 0.0f);
    rs.w = (int)fminf(ymx, (float)HH);
    g_self_rect[i] = rs;

    // --- m_br rect of index[b] (unclamped, plain trunc-to-int) ---
    int ib = index[b];
    const float* q = bbox + (size_t)(ib * TF + t) * 8;
    float xmn2 = fminf(fminf(q[0], q[2]), fminf(q[4], q[6]));
    float xmx2 = fmaxf(fmaxf(q[0], q[2]), fmaxf(q[4], q[6]));
    float ymn2 = fminf(fminf(q[1], q[3]), fminf(q[5], q[7]));
    float ymx2 = fmaxf(fmaxf(q[1], q[3]), fmaxf(q[5], q[7]));
    int4 ri;
    ri.x = (int)xmn2;
    ri.y = (int)xmx2;
    ri.z = (int)ymn2;
    ri.w = (int)ymx2;
    g_idx_rect[i] = ri;

    if (t == 0) g_index[b] = ib;
}

__global__ void __launch_bounds__(256)
fuse_kernel(const float4* __restrict__ v, float4* __restrict__ out) {
    unsigned int i = blockIdx.x * 256u + threadIdx.x;  // exact grid, no tail
    // decompose: i = (((b*CC + c)*TF + t)*HH + h)*W4 + w4
    unsigned int w4  = i % W4;
    unsigned int rem = i / W4;
    unsigned int h   = rem % HH; rem /= HH;
    unsigned int t   = rem % TF; rem /= TF;
    unsigned int c   = rem % CC;
    unsigned int b   = rem / CC;

    int bt = (int)(b * TF + t);
    int4 rs = g_self_rect[bt];
    int4 ri = g_idx_rect[bt];

    int x = (int)(w4 * 4);
    int hh = (int)h;
    bool rowS = (hh >= rs.z) & (hh <= rs.w);
    bool rowI = (hh >= ri.z) & (hh <= ri.w);

    bool m0 = rowS & (x     >= rs.x) & (x     <= rs.y);
    bool m1 = rowS & (x + 1 >= rs.x) & (x + 1 <= rs.y);
    bool m2 = rowS & (x + 2 >= rs.x) & (x + 2 <= rs.y);
    bool m3 = rowS & (x + 3 >= rs.x) & (x + 3 <= rs.y);

    bool i0 = rowI & (x     >= ri.x) & (x     <= ri.y);
    bool i1 = rowI & (x + 1 >= ri.x) & (x + 1 <= ri.y);
    bool i2 = rowI & (x + 2 >= ri.x) & (x + 2 <= ri.y);
    bool i3 = rowI & (x + 3 >= ri.x) & (x + 3 <= ri.y);

    bool needSelf = m0 | m1 | m2 | m3;
    bool needIdx  = ((!m0) & (!i0)) | ((!m1) & (!i1)) |
                    ((!m2) & (!i2)) | ((!m3) & (!i3));

    float4 vs = make_float4(0.f, 0.f, 0.f, 0.f);
    float4 vi = make_float4(0.f, 0.f, 0.f, 0.f);

    if (needSelf) vs = __ldg(v + i);
    if (needIdx) {
        unsigned int ib = (unsigned int)g_index[b];
        unsigned int ii = (((ib * CC + c) * TF + t) * HH + h) * W4 + w4;
        vi = __ldg(v + ii);
    }

    float4 o;
    o.x = m0 ? vs.x : (i0 ? 0.f : vi.x);
    o.y = m1 ? vs.y : (i1 ? 0.f : vi.y);
    o.z = m2 ? vs.z : (i2 ? 0.f : vi.z);
    o.w = m3 ? vs.w : (i3 ? 0.f : vi.w);
    out[i] = o;
}

extern "C" void kernel_launch(void* const* d_in, const int* in_sizes, int n_in,
                              void* d_out, int out_size) {
    const float* video = (const float*)d_in[0];
    const float* bbox  = (const float*)d_in[1];
    const int*   index = (const int*)d_in[2];
    float* out = (float*)d_out;

    rect_kernel<<<2, 256>>>(bbox, index);
    fuse_kernel<<<N4 / 256, 256>>>((const float4*)video, (float4*)out);
}